// round 14
// baseline (speedup 1.0000x reference)
#include <cuda_runtime.h>
#include <cuda_fp16.h>
#include <math.h>
#include <stdint.h>

// Problem constants
#define EMBED 1024
#define HEADS 16
#define HDIM  64
#define NB    4
#define LSEQ  2048
#define SCALE 0.03125f      // 1/sqrt(EMBED) = 1/32

// ---------------------------------------------------------------------------
// Scratch
// ---------------------------------------------------------------------------
__device__ __half g_Qp   [NB * HEADS * LSEQ * HDIM];  // pre-scaled by SCALE
__device__ __half g_Kp   [NB * HEADS * LSEQ * HDIM];
__device__ __half g_VpT  [NB * HEADS * HDIM * LSEQ];  // [b,h,d,l]
__device__ __half g_X    [NB * LSEQ * EMBED];         // attention out (pre-Wo)
__device__ __half g_Wo16 [EMBED * EMBED];             // fp16 Wo
__device__ __half g_Wqkv16[3 * HDIM * HDIM];          // fp16 Wq|Wk|Wv

// ---------------------------------------------------------------------------
// Helpers
// ---------------------------------------------------------------------------
__device__ __forceinline__ uint32_t smem_u32(const void* p) {
    uint32_t a;
    asm("{ .reg .u64 t; cvta.to.shared.u64 t, %1; cvt.u32.u64 %0, t; }"
        : "=r"(a) : "l"(p));
    return a;
}
__device__ __forceinline__ uint32_t lds_u32(uint32_t a) {
    uint32_t v;
    asm volatile("ld.shared.b32 %0, [%1];" : "=r"(v) : "r"(a));
    return v;
}
__device__ __forceinline__ void sts_u32(uint32_t a, uint32_t v) {
    asm volatile("st.shared.b32 [%0], %1;" :: "r"(a), "r"(v) : "memory");
}
__device__ __forceinline__ float lds_f32(uint32_t a) {
    return __uint_as_float(lds_u32(a));
}
__device__ __forceinline__ void sts_f32(uint32_t a, float v) {
    sts_u32(a, __float_as_uint(v));
}
__device__ __forceinline__ uint32_t pk2(float x, float y) {
    __half2 h = __floats2half2_rn(x, y);
    return *(uint32_t*)&h;
}

#define CP16(dst, src) asm volatile("cp.async.cg.shared.global [%0], [%1], 16;" \
                                    :: "r"(dst), "l"(src) : "memory")
#define CP_COMMIT()    asm volatile("cp.async.commit_group;" ::: "memory")
#define CP_WAIT0()     asm volatile("cp.async.wait_group 0;" ::: "memory")
#define CP_WAIT1()     asm volatile("cp.async.wait_group 1;" ::: "memory")

// 128B-row smem tile, 16B-chunk XOR swizzle.
__device__ __forceinline__ uint32_t sadr(uint32_t base, int row, int byteoff) {
    return base + row * 128 + (((byteoff >> 4) ^ (row & 7)) << 4) + (byteoff & 15);
}
__device__ __forceinline__ uint32_t ldaddr(uint32_t base, int row, int chunk) {
    return base + row * 128 + ((chunk ^ (row & 7)) << 4);
}

__device__ __forceinline__ void ldm4(uint32_t r[4], uint32_t a) {
    asm volatile("ldmatrix.sync.aligned.m8n8.x4.shared.b16 {%0,%1,%2,%3}, [%4];"
        : "=r"(r[0]), "=r"(r[1]), "=r"(r[2]), "=r"(r[3]) : "r"(a));
}

// fp16 mma m16n8k16, fp32 accumulate
__device__ __forceinline__ void mma16(float c[4], const uint32_t a[4],
                                      const uint32_t b[2]) {
    asm volatile(
        "mma.sync.aligned.m16n8k16.row.col.f32.f16.f16.f32 "
        "{%0,%1,%2,%3}, {%4,%5,%6,%7}, {%8,%9}, {%0,%1,%2,%3};"
        : "+f"(c[0]), "+f"(c[1]), "+f"(c[2]), "+f"(c[3])
        : "r"(a[0]), "r"(a[1]), "r"(a[2]), "r"(a[3]), "r"(b[0]), "r"(b[1]));
}

// Warp GEMM: acc[2][4][4] += A[rb..rb+31][0..63] @ B[cb..cb+31][0..63]^T
__device__ __forceinline__ void wgemm32(float acc[2][4][4], uint32_t A, uint32_t B,
                                        int rb, int cb, int arow, int acol,
                                        int brow, int bcol) {
#pragma unroll
    for (int ks = 0; ks < 4; ks++) {
        uint32_t a0[4], a1[4], b01[4], b23[4];
        ldm4(a0,  ldaddr(A, rb + arow,      2 * ks + acol));
        ldm4(a1,  ldaddr(A, rb + 16 + arow, 2 * ks + acol));
        ldm4(b01, ldaddr(B, cb + brow,      2 * ks + bcol));
        ldm4(b23, ldaddr(B, cb + 16 + brow, 2 * ks + bcol));
        mma16(acc[0][0], a0, b01);
        mma16(acc[0][1], a0, b01 + 2);
        mma16(acc[0][2], a0, b23);
        mma16(acc[0][3], a0, b23 + 2);
        mma16(acc[1][0], a1, b01);
        mma16(acc[1][1], a1, b01 + 2);
        mma16(acc[1][2], a1, b23);
        mma16(acc[1][3], a1, b23 + 2);
    }
}

// ---------------------------------------------------------------------------
// Kernel 0: weight conversions (Wo + Wq/Wk/Wv -> fp16)
// ---------------------------------------------------------------------------
__global__ __launch_bounds__(256) void wcvt_kernel(
    const float* __restrict__ Wo, const float* __restrict__ Wq,
    const float* __restrict__ Wk, const float* __restrict__ Wv)
{
    const int bx = blockIdx.x;
    if (bx < 1024) {
        const int i = (bx * 256 + threadIdx.x) * 4;
        float4 v = *(const float4*)(Wo + i);
        *(__half2*)(g_Wo16 + i)     = __floats2half2_rn(v.x, v.y);
        *(__half2*)(g_Wo16 + i + 2) = __floats2half2_rn(v.z, v.w);
    } else {
        const int j = bx - 1024;
        const int which = j >> 2;
        const float* src = (which == 0) ? Wq : (which == 1) ? Wk : Wv;
        const int off = (j & 3) * 1024 + threadIdx.x * 4;
        float4 v = *(const float4*)(src + off);
        __half* dst = g_Wqkv16 + which * 4096 + off;
        *(__half2*)(dst)     = __floats2half2_rn(v.x, v.y);
        *(__half2*)(dst + 2) = __floats2half2_rn(v.z, v.w);
    }
}

// ---------------------------------------------------------------------------
// Kernel 1: QKV per-head projection on fp16 HMMA (unchanged).
// ---------------------------------------------------------------------------
__global__ __launch_bounds__(256) void proj_kernel(
    const float* __restrict__ q, const float* __restrict__ k,
    const float* __restrict__ v)
{
    __shared__ __align__(16) char psm[16384 + 8192];
    const uint32_t sb = smem_u32(psm);
    const uint32_t X = sb, W = sb + 16384u;

    const int l0    = blockIdx.x * 128;
    const int which = blockIdx.y / HEADS;
    const int h     = blockIdx.y % HEADS;
    const int b     = blockIdx.z;

    const float* src; float oscale;
    if (which == 0)      { src = q; oscale = SCALE; }
    else if (which == 1) { src = k; oscale = 1.0f;  }
    else                 { src = v; oscale = 1.0f;  }

    const int tid  = threadIdx.x;
    const int wid  = tid >> 5;
    const int lane = tid & 31;
    const int g = lane >> 2, t = lane & 3;
    const int wr = wid >> 1, wc = wid & 1;
    const int arow = (lane & 7) + ((lane >> 3) & 1) * 8, acol = (lane >> 4) & 1;
    const int brow = (lane & 7) + ((lane >> 4) & 1) * 8, bcol = (lane >> 3) & 1;

    const __half* wsrc = g_Wqkv16 + which * 4096;
    for (int i = tid; i < 512; i += 256) {
        int row = i >> 3, c = i & 7;
        CP16(sadr(W, row, c << 4), wsrc + row * HDIM + c * 8);
    }
    CP_COMMIT();

    const float* abase = src + ((size_t)b * LSEQ + l0) * EMBED + h * HDIM;
    for (int i = tid; i < 128 * 16; i += 256) {
        int row = i >> 4, c4 = (i & 15) << 2;
        float4 x = *(const float4*)(abase + (size_t)row * EMBED + c4);
        sts_u32(sadr(X, row, c4 * 2),     pk2(x.x, x.y));
        sts_u32(sadr(X, row, c4 * 2 + 4), pk2(x.z, x.w));
    }
    CP_WAIT0();
    __syncthreads();

    float acc[2][4][4];
#pragma unroll
    for (int rg = 0; rg < 2; rg++)
#pragma unroll
        for (int nt = 0; nt < 4; nt++)
#pragma unroll
            for (int j = 0; j < 4; j++) acc[rg][nt][j] = 0.0f;

    wgemm32(acc, X, W, wr * 32, wc * 32, arow, acol, brow, bcol);

    const size_t bh = (size_t)(b * HEADS + h);
    if (which == 2) {
        __half* vt = g_VpT + bh * HDIM * LSEQ;
#pragma unroll
        for (int rg = 0; rg < 2; rg++)
#pragma unroll
            for (int nt = 0; nt < 4; nt++) {
                int col = wc * 32 + nt * 8 + 2 * t;
                int r0 = l0 + wr * 32 + rg * 16 + g;
                vt[(size_t)col       * LSEQ + r0]     = __float2half_rn(acc[rg][nt][0]);
                vt[(size_t)(col + 1) * LSEQ + r0]     = __float2half_rn(acc[rg][nt][1]);
                vt[(size_t)col       * LSEQ + r0 + 8] = __float2half_rn(acc[rg][nt][2]);
                vt[(size_t)(col + 1) * LSEQ + r0 + 8] = __float2half_rn(acc[rg][nt][3]);
            }
    } else {
        __half* dst = (which == 0) ? g_Qp : g_Kp;
        __half* dbase = dst + (bh * LSEQ + l0) * HDIM;
#pragma unroll
        for (int rg = 0; rg < 2; rg++)
#pragma unroll
            for (int nt = 0; nt < 4; nt++) {
                int col = wc * 32 + nt * 8 + 2 * t;
                int r0 = wr * 32 + rg * 16 + g;
                *(__half2*)(dbase + (size_t)r0 * HDIM + col) =
                    __floats2half2_rn(acc[rg][nt][0] * oscale, acc[rg][nt][1] * oscale);
                *(__half2*)(dbase + (size_t)(r0 + 8) * HDIM + col) =
                    __floats2half2_rn(acc[rg][nt][2] * oscale, acc[rg][nt][3] * oscale);
            }
    }
}

// ---------------------------------------------------------------------------
// Kernel 2: flash attention, FA2-style P-in-registers, 3-STAGE K/V pipeline.
// smem (64KB dyn): Q@0(16K), K{0,1,2}@16K+8K*buf, V{0,1,2}@40K+8K*buf.
// Epilogue reuses 16K..48K for the O pair-reduction, 0..512 for l.
// ---------------------------------------------------------------------------
#define AOQ       0u
#define AOK(buf)  (16384u + (uint32_t)(buf) * 8192u)
#define AOV(buf)  (40960u + (uint32_t)(buf) * 8192u)
#define ATTN_SMEM 65536

__global__ __launch_bounds__(256, 2) void attn_kernel()
{
    extern __shared__ __half smh[];
    const uint32_t sb = smem_u32(smh);

    const int q0 = blockIdx.x * 128;
    const int h  = blockIdx.y;
    const int b  = blockIdx.z;
    const int tid  = threadIdx.x;
    const int wid  = tid >> 5;
    const int lane = tid & 31;
    const int g = lane >> 2, t = lane & 3;
    const int wr = wid >> 1, wc = wid & 1;
    const int rb = wr * 32, cb = wc * 32;
    const int arow = (lane & 7) + ((lane >> 3) & 1) * 8, acol = (lane >> 4) & 1;
    const int brow = (lane & 7) + ((lane >> 4) & 1) * 8, bcol = (lane >> 3) & 1;

    const size_t bh = (size_t)(b * HEADS + h);
    const __half* Qg = g_Qp  + (bh * LSEQ + q0) * HDIM;
    const __half* Kg = g_Kp  + bh * LSEQ * HDIM;
    const __half* Vt = g_VpT + bh * HDIM * LSEQ;

    // Prologue: group 0 = Q + K0/V0; group 1 = K1/V1.
    for (int i = tid; i < 1024; i += 256) {
        int row = i >> 3, c = i & 7;
        CP16(sadr(sb + AOQ, row, c << 4), Qg + row * HDIM + c * 8);
    }
    for (int i = tid; i < 512; i += 256) {
        int row = i >> 3, c = i & 7;
        CP16(sadr(sb + AOK(0), row, c << 4), Kg + row * HDIM + c * 8);
        CP16(sadr(sb + AOV(0), row, c << 4), Vt + (size_t)row * LSEQ + c * 8);
    }
    CP_COMMIT();
    {
        const __half* kg = Kg + (size_t)64 * HDIM;
        const __half* vt = Vt + 64;
        for (int i = tid; i < 512; i += 256) {
            int row = i >> 3, c = i & 7;
            CP16(sadr(sb + AOK(1), row, c << 4), kg + row * HDIM + c * 8);
            CP16(sadr(sb + AOV(1), row, c << 4), vt + (size_t)row * LSEQ + c * 8);
        }
        CP_COMMIT();
    }

    float O[2][8][4];
#pragma unroll
    for (int rg = 0; rg < 2; rg++)
#pragma unroll
        for (int nt = 0; nt < 8; nt++)
#pragma unroll
            for (int j = 0; j < 4; j++) O[rg][nt][j] = 0.0f;
    float ls[2][2] = {{0.0f, 0.0f}, {0.0f, 0.0f}};

    for (int kt = 0; kt < 32; kt++) {
        const int buf = kt % 3;
        if (kt + 1 < 32) { CP_WAIT1(); } else { CP_WAIT0(); }
        __syncthreads();   // tile kt ready; all warps done with buffer (kt+2)%3

        if (kt + 2 < 32) {
            const int nbuf = (kt + 2) % 3;
            const __half* kg = Kg + (size_t)(kt + 2) * 64 * HDIM;
            const __half* vt = Vt + (size_t)(kt + 2) * 64;
            for (int i = tid; i < 512; i += 256) {
                int row = i >> 3, c = i & 7;
                CP16(sadr(sb + AOK(nbuf), row, c << 4), kg + row * HDIM + c * 8);
                CP16(sadr(sb + AOV(nbuf), row, c << 4), vt + (size_t)row * LSEQ + c * 8);
            }
            CP_COMMIT();
        }

        float S[2][4][4];
#pragma unroll
        for (int rg = 0; rg < 2; rg++)
#pragma unroll
            for (int nt = 0; nt < 4; nt++)
#pragma unroll
                for (int j = 0; j < 4; j++) S[rg][nt][j] = 0.0f;
        wgemm32(S, sb + AOQ, sb + AOK(buf), rb, cb, arow, acol, brow, bcol);

#pragma unroll
        for (int rg = 0; rg < 2; rg++)
#pragma unroll
            for (int nt = 0; nt < 4; nt++) {
                S[rg][nt][0] = __expf(S[rg][nt][0]);
                S[rg][nt][1] = __expf(S[rg][nt][1]);
                S[rg][nt][2] = __expf(S[rg][nt][2]);
                S[rg][nt][3] = __expf(S[rg][nt][3]);
                ls[rg][0] += S[rg][nt][0] + S[rg][nt][1];
                ls[rg][1] += S[rg][nt][2] + S[rg][nt][3];
            }

#pragma unroll
        for (int ks = 0; ks < 2; ks++) {
            uint32_t pa[2][4];
#pragma unroll
            for (int rg = 0; rg < 2; rg++) {
                pa[rg][0] = pk2(S[rg][2 * ks][0],     S[rg][2 * ks][1]);
                pa[rg][1] = pk2(S[rg][2 * ks][2],     S[rg][2 * ks][3]);
                pa[rg][2] = pk2(S[rg][2 * ks + 1][0], S[rg][2 * ks + 1][1]);
                pa[rg][3] = pk2(S[rg][2 * ks + 1][2], S[rg][2 * ks + 1][3]);
            }
#pragma unroll
            for (int nt2 = 0; nt2 < 4; nt2++) {
                uint32_t bb[4];
                ldm4(bb, ldaddr(sb + AOV(buf), nt2 * 16 + brow,
                                wc * 4 + 2 * ks + bcol));
                mma16(O[0][2 * nt2],     pa[0], bb);
                mma16(O[0][2 * nt2 + 1], pa[0], bb + 2);
                mma16(O[1][2 * nt2],     pa[1], bb);
                mma16(O[1][2 * nt2 + 1], pa[1], bb + 2);
            }
        }
    }

#pragma unroll
    for (int rg = 0; rg < 2; rg++)
#pragma unroll
        for (int hh = 0; hh < 2; hh++) {
            ls[rg][hh] += __shfl_xor_sync(0xFFFFFFFFu, ls[rg][hh], 1);
            ls[rg][hh] += __shfl_xor_sync(0xFFFFFFFFu, ls[rg][hh], 2);
        }
    __syncthreads();

    if (wc == 1) {
        const uint32_t obase = sb + 16384u + (uint32_t)wr * 8192u;
#pragma unroll
        for (int rg = 0; rg < 2; rg++)
#pragma unroll
            for (int nt = 0; nt < 8; nt++) {
                int col = nt * 8 + 2 * t;
                int r0 = rg * 16 + g;
                uint32_t a0 = obase + (uint32_t)(r0 * 256 + col * 4);
                sts_f32(a0,     O[rg][nt][0]);
                sts_f32(a0 + 4, O[rg][nt][1]);
                uint32_t a1 = obase + (uint32_t)((r0 + 8) * 256 + col * 4);
                sts_f32(a1,     O[rg][nt][2]);
                sts_f32(a1 + 4, O[rg][nt][3]);
            }
#pragma unroll
        for (int rg = 0; rg < 2; rg++)
#pragma unroll
            for (int hh = 0; hh < 2; hh++)
                sts_f32(sb + (uint32_t)(wr * 32 + rg * 16 + g + 8 * hh) * 4,
                        ls[rg][hh]);
    }
    __syncthreads();

    if (wc == 0) {
        const uint32_t obase = sb + 16384u + (uint32_t)wr * 8192u;
        __half* xg = g_X + (size_t)(b * LSEQ + q0) * EMBED + h * HDIM;
#pragma unroll
        for (int rg = 0; rg < 2; rg++) {
            float inv0 = 1.0f / (ls[rg][0] +
                lds_f32(sb + (uint32_t)(wr * 32 + rg * 16 + g) * 4));
            float inv1 = 1.0f / (ls[rg][1] +
                lds_f32(sb + (uint32_t)(wr * 32 + rg * 16 + g + 8) * 4));
#pragma unroll
            for (int nt = 0; nt < 8; nt++) {
                int col = nt * 8 + 2 * t;
                int r0 = rg * 16 + g;
                uint32_t a0 = obase + (uint32_t)(r0 * 256 + col * 4);
                float o0 = (O[rg][nt][0] + lds_f32(a0))     * inv0;
                float o1 = (O[rg][nt][1] + lds_f32(a0 + 4)) * inv0;
                uint32_t a1 = obase + (uint32_t)((r0 + 8) * 256 + col * 4);
                float o2 = (O[rg][nt][2] + lds_f32(a1))     * inv1;
                float o3 = (O[rg][nt][3] + lds_f32(a1 + 4)) * inv1;
                *(__half2*)(xg + (size_t)(rb + r0) * EMBED + col) =
                    __floats2half2_rn(o0, o1);
                *(__half2*)(xg + (size_t)(rb + r0 + 8) * EMBED + col) =
                    __floats2half2_rn(o2, o3);
            }
        }
    }
}

// ---------------------------------------------------------------------------
// Kernel 3: output projection — 3-STAGE pipeline.
// CTA tile 128 tokens x 128 outs; k-chunks of 64.
// smem (96KB dyn): X{0,1,2}@32K*buf, W{0,1,2}@16K+32K*buf.
// ---------------------------------------------------------------------------
#define OPX(buf)  ((uint32_t)(buf) * 32768u)
#define OPW(buf)  (16384u + (uint32_t)(buf) * 32768u)
#define OP_SMEM   98304

__global__ __launch_bounds__(256, 2) void oproj_kernel(
    const float* __restrict__ bo, float* __restrict__ out)
{
    extern __shared__ __half smo[];
    const uint32_t sb = smem_u32(smo);

    const int t0 = blockIdx.x * 128;
    const int n0 = blockIdx.y * 128;
    const int tid  = threadIdx.x;
    const int wid  = tid >> 5;
    const int lane = tid & 31;
    const int g = lane >> 2, t = lane & 3;
    const int wr = wid >> 1, wc = wid & 1;

    const __half* Xg = g_X    + (size_t)t0 * EMBED;
    const __half* Wg = g_Wo16 + (size_t)n0 * EMBED;

    // Prologue: chunks 0 and 1 as two groups
#pragma unroll
    for (int pc = 0; pc < 2; pc++) {
        const int k0 = pc * 64;
        for (int i = tid; i < 1024; i += 256) {
            int row = i >> 3, c = i & 7;
            CP16(sadr(sb + OPX(pc), row, c << 4),
                 Xg + (size_t)row * EMBED + k0 + c * 8);
            CP16(sadr(sb + OPW(pc), row, c << 4),
                 Wg + (size_t)row * EMBED + k0 + c * 8);
        }
        CP_COMMIT();
    }

    float acc[2][8][4];
#pragma unroll
    for (int rg = 0; rg < 2; rg++)
#pragma unroll
        for (int nt = 0; nt < 8; nt++)
#pragma unroll
            for (int j = 0; j < 4; j++) acc[rg][nt][j] = 0.0f;

    for (int kc = 0; kc < 16; kc++) {
        const int buf = kc % 3;
        if (kc + 1 < 16) { CP_WAIT1(); } else { CP_WAIT0(); }
        __syncthreads();   // chunk kc ready; buffer (kc+2)%3 free

        if (kc + 2 < 16) {
            const int nbuf = (kc + 2) % 3;
            const int k0 = (kc + 2) * 64;
            for (int i = tid; i < 1024; i += 256) {
                int row = i >> 3, c = i & 7;
                CP16(sadr(sb + OPX(nbuf), row, c << 4),
                     Xg + (size_t)row * EMBED + k0 + c * 8);
                CP16(sadr(sb + OPW(nbuf), row, c << 4),
                     Wg + (size_t)row * EMBED + k0 + c * 8);
            }
            CP_COMMIT();
        }

        const uint32_t X = sb + OPX(buf), W = sb + OPW(buf);
#pragma unroll
        for (int ks = 0; ks < 4; ks++) {
            const int by = ks * 32 + 4 * t;
            uint32_t a0[4], a1[4];
            a0[0] = lds_u32(sadr(X, wr * 32 + g,      by));
            a0[1] = lds_u32(sadr(X, wr * 32 + g + 8,  by));
            a0[2] = lds_u32(sadr(X, wr * 32 + g,      by + 16));
            a0[3] = lds_u32(sadr(X, wr * 32 + g + 8,  by + 16));
            a1[0] = lds_u32(sadr(X, wr * 32 + 16 + g,     by));
            a1[1] = lds_u32(sadr(X, wr * 32 + 16 + g + 8, by));
            a1[2] = lds_u32(sadr(X, wr * 32 + 16 + g,     by + 16));
            a1[3] = lds_u32(sadr(X, wr * 32 + 16 + g + 8, by + 16));
#pragma unroll
            for (int nt = 0; nt < 8; nt++) {
                uint32_t bfr[2];
                bfr[0] = lds_u32(sadr(W, wc * 64 + nt * 8 + g, by));
                bfr[1] = lds_u32(sadr(W, wc * 64 + nt * 8 + g, by + 16));
                mma16(acc[0][nt], a0, bfr);
                mma16(acc[1][nt], a1, bfr);
            }
        }
    }

#pragma unroll
    for (int rg = 0; rg < 2; rg++)
#pragma unroll
        for (int nt = 0; nt < 8; nt++) {
            int col = n0 + wc * 64 + nt * 8 + 2 * t;
            float b0v = bo[col], b1v = bo[col + 1];
            int r0 = t0 + wr * 32 + rg * 16 + g;
            *(float2*)(out + (size_t)r0 * EMBED + col) =
                make_float2(acc[rg][nt][0] + b0v, acc[rg][nt][1] + b1v);
            *(float2*)(out + (size_t)(r0 + 8) * EMBED + col) =
                make_float2(acc[rg][nt][2] + b0v, acc[rg][nt][3] + b1v);
        }
}

// ---------------------------------------------------------------------------
extern "C" void kernel_launch(void* const* d_in, const int* in_sizes, int n_in,
                              void* d_out, int out_size)
{
    const float* values  = (const float*)d_in[0];
    const float* keys    = (const float*)d_in[1];
    const float* queries = (const float*)d_in[2];
    const float* Wv      = (const float*)d_in[3];
    const float* Wk      = (const float*)d_in[4];
    const float* Wq      = (const float*)d_in[5];
    const float* Wo      = (const float*)d_in[6];
    const float* bo      = (const float*)d_in[7];
    float* out = (float*)d_out;

    wcvt_kernel<<<1036, 256>>>(Wo, Wq, Wk, Wv);

    proj_kernel<<<dim3(LSEQ / 128, 3 * HEADS, NB), 256>>>(queries, keys, values);

    cudaFuncSetAttribute(attn_kernel,
                         cudaFuncAttributeMaxDynamicSharedMemorySize, ATTN_SMEM);
    attn_kernel<<<dim3(LSEQ / 128, HEADS, NB), 256, ATTN_SMEM>>>();

    cudaFuncSetAttribute(oproj_kernel,
                         cudaFuncAttributeMaxDynamicSharedMemorySize, OP_SMEM);
    oproj_kernel<<<dim3(NB * LSEQ / 128, EMBED / 128), 256, OP_SMEM>>>(bo, out);
}